// round 4
// baseline (speedup 1.0000x reference)
#include <cuda_runtime.h>
#include <cuda_bf16.h>
#include <cstdint>

#define N_NODES 50000
#define N_EDGES 800000
#define HID 64
#define N_CLS 16
#define MAX_DEG 64

// Scratch (device globals — no allocation allowed)
__device__ int   g_cnt[N_NODES];                      // in-degree (atomic cursor)
__device__ int   g_adj[N_NODES * MAX_DEG];            // bucketed adjacency (src per dst)
__device__ __align__(16) float g_h[N_NODES * HID];    // layer-1 output
__device__ __align__(16) float g_p[N_NODES * N_CLS];  // h @ W2_l (pre-projected messages)

// ---------------------------------------------------------------------------
// Zero the degree counters only (no more 16MB accumulator zeroing)
// ---------------------------------------------------------------------------
__global__ void zero_cnt_k() {
    int i = blockIdx.x * blockDim.x + threadIdx.x;
    if (i < N_NODES) g_cnt[i] = 0;
}

// ---------------------------------------------------------------------------
// Build bucketed adjacency: for each edge (s -> d), append s to d's list.
// edge_index is int32 (JAX x64 disabled).
// ---------------------------------------------------------------------------
__global__ void fill_k(const int* __restrict__ ei) {
    int e = blockIdx.x * blockDim.x + threadIdx.x;
    if (e >= N_EDGES) return;
    int s = ei[e];
    int d = ei[N_EDGES + e];
    if ((unsigned)s >= N_NODES || (unsigned)d >= N_NODES) return;
    int pos = atomicAdd(&g_cnt[d], 1);
    if (pos < MAX_DEG) g_adj[d * MAX_DEG + pos] = s;
}

// ---------------------------------------------------------------------------
// Layer 1 fused: gather mean(x_j) per node (no atomics), then
//   h = relu(mean @ W1_l + x @ W1_r + b1);  p = h @ W2_l
// Block = 128 threads = 4 warps; each warp owns 4 nodes per iteration.
// Gather: lane = g*16 + f; g in {0,1} = neighbor slot, f = float4 position.
// ---------------------------------------------------------------------------
__global__ void layer1_k(const float* __restrict__ x,
                         const float* __restrict__ W1l,
                         const float* __restrict__ b1,
                         const float* __restrict__ W1r,
                         const float* __restrict__ W2l) {
    __shared__ float sWl[64 * 64];
    __shared__ float sWr[64 * 64];
    __shared__ float sW2[64 * 16];
    __shared__ float sb1[64];
    __shared__ float sX[4][4][64];
    __shared__ float sM[4][4][64];   // mean rows; reused for h rows

    int tid = threadIdx.x, warp = tid >> 5, lane = tid & 31;
    for (int i = tid; i < 4096; i += 128) { sWl[i] = W1l[i]; sWr[i] = W1r[i]; }
    for (int i = tid; i < 1024; i += 128) sW2[i] = W2l[i];
    if (tid < 64) sb1[tid] = b1[tid];
    __syncthreads();

    const float4* x4 = reinterpret_cast<const float4*>(x);
    int g = lane >> 4;      // neighbor slot 0/1
    int f = lane & 15;      // float4 position within 64-float row

    for (int nb = (blockIdx.x * 4 + warp) * 4; nb < N_NODES; nb += gridDim.x * 16) {
        int nvalid = min(4, N_NODES - nb);

        // Gather means + load own x rows
        for (int q = 0; q < nvalid; q++) {
            int node = nb + q;
            size_t r = (size_t)node * 64;
            sX[warp][q][lane]      = x[r + lane];
            sX[warp][q][lane + 32] = x[r + lane + 32];

            int c = g_cnt[node];
            int cl = min(c, MAX_DEG);
            const int* row = g_adj + (size_t)node * MAX_DEG;
            float4 acc = make_float4(0.f, 0.f, 0.f, 0.f);
#pragma unroll 2
            for (int j = g; j < cl; j += 2) {
                int src = __ldg(row + j);
                float4 v = x4[(size_t)src * 16 + f];
                acc.x += v.x; acc.y += v.y; acc.z += v.z; acc.w += v.w;
            }
            acc.x += __shfl_xor_sync(0xffffffff, acc.x, 16);
            acc.y += __shfl_xor_sync(0xffffffff, acc.y, 16);
            acc.z += __shfl_xor_sync(0xffffffff, acc.z, 16);
            acc.w += __shfl_xor_sync(0xffffffff, acc.w, 16);
            float invd = 1.0f / fmaxf((float)c, 1.0f);
            if (g == 0) {
                *reinterpret_cast<float4*>(&sM[warp][q][f * 4]) =
                    make_float4(acc.x * invd, acc.y * invd, acc.z * invd, acc.w * invd);
            }
        }
        __syncwarp();

        float a0[4], a1[4];
#pragma unroll
        for (int q = 0; q < 4; q++) { a0[q] = sb1[lane]; a1[q] = sb1[lane + 32]; }

#pragma unroll
        for (int k4 = 0; k4 < 64; k4 += 4) {
            float4 mv[4], xv[4];
#pragma unroll
            for (int q = 0; q < 4; q++) {
                mv[q] = *reinterpret_cast<const float4*>(&sM[warp][q][k4]);
                xv[q] = *reinterpret_cast<const float4*>(&sX[warp][q][k4]);
            }
#pragma unroll
            for (int kk = 0; kk < 4; kk++) {
                int k = k4 + kk;
                float wl0 = sWl[k * 64 + lane];
                float wl1 = sWl[k * 64 + lane + 32];
                float wr0 = sWr[k * 64 + lane];
                float wr1 = sWr[k * 64 + lane + 32];
#pragma unroll
                for (int q = 0; q < 4; q++) {
                    float m  = (kk == 0) ? mv[q].x : (kk == 1) ? mv[q].y : (kk == 2) ? mv[q].z : mv[q].w;
                    float xx = (kk == 0) ? xv[q].x : (kk == 1) ? xv[q].y : (kk == 2) ? xv[q].z : xv[q].w;
                    a0[q] = fmaf(m, wl0, a0[q]);
                    a0[q] = fmaf(xx, wr0, a0[q]);
                    a1[q] = fmaf(m, wl1, a1[q]);
                    a1[q] = fmaf(xx, wr1, a1[q]);
                }
            }
        }
        __syncwarp();   // all lanes done reading sM before overwrite

#pragma unroll
        for (int q = 0; q < 4; q++) {
            if (q < nvalid) {
                float h0 = fmaxf(a0[q], 0.f);
                float h1 = fmaxf(a1[q], 0.f);
                size_t r = (size_t)(nb + q) * 64;
                g_h[r + lane]      = h0;
                g_h[r + lane + 32] = h1;
                sM[warp][q][lane]      = h0;
                sM[warp][q][lane + 32] = h1;
            }
        }
        __syncwarp();

        {   // p = h @ W2_l : lane -> (node = lane>>3, col pair = lane&7)
            int n = lane >> 3, c0 = (lane & 7) * 2;
            if (n < nvalid) {
                float p0 = 0.f, p1 = 0.f;
#pragma unroll
                for (int k = 0; k < 64; k++) {
                    float hv = sM[warp][n][k];
                    p0 = fmaf(hv, sW2[k * 16 + c0], p0);
                    p1 = fmaf(hv, sW2[k * 16 + c0 + 1], p1);
                }
                size_t node = (size_t)(nb + n);
                g_p[node * 16 + c0]     = p0;
                g_p[node * 16 + c0 + 1] = p1;
            }
        }
        __syncwarp();
    }
}

// ---------------------------------------------------------------------------
// Final fused: out = mean_j(p_j) + h @ W2_r + b2
// Block = 128 = 4 warps, warp handles 4 nodes; 8 lanes per node, each lane
// owns 2 classes and gathers exactly its 8 bytes per neighbor (no atomics).
// ---------------------------------------------------------------------------
__global__ void final_k(const float* __restrict__ W2r,
                        const float* __restrict__ b2,
                        float* __restrict__ out) {
    __shared__ float sW[64 * 16];
    __shared__ float sb[16];
    __shared__ float sh[4][4][64];
    int tid = threadIdx.x, warp = tid >> 5, lane = tid & 31;
    for (int i = tid; i < 1024; i += 128) sW[i] = W2r[i];
    if (tid < 16) sb[tid] = b2[tid];
    __syncthreads();

    int n = lane >> 3, c0 = (lane & 7) * 2;
    for (int nb = (blockIdx.x * 4 + warp) * 4; nb < N_NODES; nb += gridDim.x * 16) {
        int nvalid = min(4, N_NODES - nb);
        for (int q = 0; q < nvalid; q++) {
            size_t r = (size_t)(nb + q) * 64;
            sh[warp][q][lane]      = g_h[r + lane];
            sh[warp][q][lane + 32] = g_h[r + lane + 32];
        }
        __syncwarp();
        if (n < nvalid) {
            int node = nb + n;
            int c = g_cnt[node];
            int cl = min(c, MAX_DEG);
            const int* row = g_adj + (size_t)node * MAX_DEG;
            float s0 = 0.f, s1 = 0.f;
#pragma unroll 4
            for (int j = 0; j < cl; j++) {
                int src = __ldg(row + j);
                float2 v = *reinterpret_cast<const float2*>(g_p + (size_t)src * 16 + c0);
                s0 += v.x; s1 += v.y;
            }
            float invd = 1.0f / fmaxf((float)c, 1.0f);
            float p0 = sb[c0]     + s0 * invd;
            float p1 = sb[c0 + 1] + s1 * invd;
#pragma unroll
            for (int k = 0; k < 64; k++) {
                float hv = sh[warp][n][k];
                p0 = fmaf(hv, sW[k * 16 + c0], p0);
                p1 = fmaf(hv, sW[k * 16 + c0 + 1], p1);
            }
            out[(size_t)node * 16 + c0]     = p0;
            out[(size_t)node * 16 + c0 + 1] = p1;
        }
        __syncwarp();
    }
}

// ---------------------------------------------------------------------------
extern "C" void kernel_launch(void* const* d_in, const int* in_sizes, int n_in,
                              void* d_out, int out_size) {
    const float* x   = (const float*)d_in[0];
    const int*   ei  = (const int*)d_in[1];     // int32! (JAX x64 disabled)
    const float* W1l = (const float*)d_in[2];
    const float* b1  = (const float*)d_in[3];
    const float* W1r = (const float*)d_in[4];
    const float* W2l = (const float*)d_in[5];
    const float* b2  = (const float*)d_in[6];
    const float* W2r = (const float*)d_in[7];
    float* out = (float*)d_out;

    zero_cnt_k<<<(N_NODES + 255) / 256, 256>>>();
    fill_k<<<(N_EDGES + 255) / 256, 256>>>(ei);
    layer1_k<<<592, 128>>>(x, W1l, b1, W1r, W2l);
    final_k<<<592, 128>>>(W2r, b2, out);
}

// round 5
// speedup vs baseline: 1.2287x; 1.2287x over previous
#include <cuda_runtime.h>
#include <cuda_bf16.h>
#include <cstdint>

#define N_NODES 50000
#define N_EDGES 800000
#define HID 64
#define N_CLS 16
#define MAX_DEG 64

// Scratch (device globals — no allocation allowed)
__device__ int   g_cnt[N_NODES];
__device__ int   g_adj[N_NODES * MAX_DEG];
__device__ __align__(16) float g_mean[N_NODES * HID];   // mean of x[src] per dst
__device__ __align__(16) float g_h[N_NODES * HID];      // layer-1 output
__device__ __align__(16) float g_p[N_NODES * N_CLS];    // h @ W2_l
__device__ __align__(16) float g_pm[N_NODES * N_CLS];   // mean of p[src] per dst

// ---- packed f32x2 helpers (Blackwell FFMA2) --------------------------------
__device__ __forceinline__ unsigned long long pk(float a, float b) {
    unsigned long long r;
    asm("mov.b64 %0, {%1, %2};" : "=l"(r) : "f"(a), "f"(b));
    return r;
}
__device__ __forceinline__ void fma2(unsigned long long& d,
                                     unsigned long long a, unsigned long long b) {
    asm("fma.rn.f32x2 %0, %1, %2, %0;" : "+l"(d) : "l"(a), "l"(b));
}
__device__ __forceinline__ float2 upk(unsigned long long v) {
    float2 f;
    asm("mov.b64 {%0, %1}, %2;" : "=f"(f.x), "=f"(f.y) : "l"(v));
    return f;
}

// ---------------------------------------------------------------------------
__global__ void zero_cnt_k() {
    int i = blockIdx.x * blockDim.x + threadIdx.x;
    if (i < N_NODES) g_cnt[i] = 0;
}

__global__ void fill_k(const int* __restrict__ ei) {
    int e = blockIdx.x * blockDim.x + threadIdx.x;
    if (e >= N_EDGES) return;
    int s = ei[e];
    int d = ei[N_EDGES + e];
    if ((unsigned)s >= N_NODES || (unsigned)d >= N_NODES) return;
    int pos = atomicAdd(&g_cnt[d], 1);
    if (pos < MAX_DEG) g_adj[d * MAX_DEG + pos] = s;
}

// ---------------------------------------------------------------------------
// High-MLP mean gather: thread = (node, float4-chunk). 4 independent row loads
// per iteration (indices fetched as int4), separate accumulators.
// SEL: 0 -> src = x (input arg), dst = g_mean, W4=16
//      1 -> src = g_p,           dst = g_pm,   W4=4
// ---------------------------------------------------------------------------
template<int SEL, int LOG_W4>
__global__ void gather_mean_k(const float4* __restrict__ xin) {
    constexpr int W4 = 1 << LOG_W4;
    const float4* src = (SEL == 0) ? xin : reinterpret_cast<const float4*>(g_p);
    float4* dst = (SEL == 0) ? reinterpret_cast<float4*>(g_mean)
                             : reinterpret_cast<float4*>(g_pm);
    int t = blockIdx.x * blockDim.x + threadIdx.x;
    int node = t >> LOG_W4;
    int f = t & (W4 - 1);
    if (node >= N_NODES) return;
    int c = g_cnt[node];
    int cl = min(c, MAX_DEG);
    const int4* row4 = reinterpret_cast<const int4*>(g_adj + (size_t)node * MAX_DEG);
    float4 a0 = make_float4(0.f,0.f,0.f,0.f), a1 = a0, a2 = a0, a3 = a0;
    int nfull = cl >> 2;
#pragma unroll 2
    for (int j4 = 0; j4 < nfull; j4++) {
        int4 idx = __ldg(row4 + j4);
        float4 v0 = __ldg(src + (((size_t)idx.x) << LOG_W4) + f);
        float4 v1 = __ldg(src + (((size_t)idx.y) << LOG_W4) + f);
        float4 v2 = __ldg(src + (((size_t)idx.z) << LOG_W4) + f);
        float4 v3 = __ldg(src + (((size_t)idx.w) << LOG_W4) + f);
        a0.x += v0.x; a0.y += v0.y; a0.z += v0.z; a0.w += v0.w;
        a1.x += v1.x; a1.y += v1.y; a1.z += v1.z; a1.w += v1.w;
        a2.x += v2.x; a2.y += v2.y; a2.z += v2.z; a2.w += v2.w;
        a3.x += v3.x; a3.y += v3.y; a3.z += v3.z; a3.w += v3.w;
    }
    for (int j = nfull * 4; j < cl; j++) {
        int s = __ldg(g_adj + (size_t)node * MAX_DEG + j);
        float4 v = __ldg(src + (((size_t)s) << LOG_W4) + f);
        a0.x += v.x; a0.y += v.y; a0.z += v.z; a0.w += v.w;
    }
    float invd = 1.0f / fmaxf((float)c, 1.0f);
    float4 r;
    r.x = (a0.x + a1.x + a2.x + a3.x) * invd;
    r.y = (a0.y + a1.y + a2.y + a3.y) * invd;
    r.z = (a0.z + a1.z + a2.z + a3.z) * invd;
    r.w = (a0.w + a1.w + a2.w + a3.w) * invd;
    dst[((size_t)node << LOG_W4) + f] = r;
}

// ---------------------------------------------------------------------------
// Layer 1 GEMM (packed f32x2): h = relu(mean @ W1_l + x @ W1_r + b1); p = h @ W2_l
// ---------------------------------------------------------------------------
__global__ void layer1_k(const float* __restrict__ x,
                         const float* __restrict__ W1l,
                         const float* __restrict__ b1,
                         const float* __restrict__ W1r,
                         const float* __restrict__ W2l) {
    __shared__ float2 sWA[64][64];          // (wl, wr) per (k, col)   32KB
    __shared__ float  sW2[64 * 16];         // 4KB
    __shared__ float  sb1[64];
    __shared__ float2 sMX[4][8][64];        // (mean, x) per (warp,q,k) 16KB

    int tid = threadIdx.x, warp = tid >> 5, lane = tid & 31;
    for (int i = tid; i < 4096; i += 128) {
        int k = i >> 6, c = i & 63;
        sWA[k][c] = make_float2(W1l[i], W1r[i]);
    }
    for (int i = tid; i < 1024; i += 128) sW2[i] = W2l[i];
    if (tid < 64) sb1[tid] = b1[tid];
    __syncthreads();

    for (int nb0 = blockIdx.x * 32; nb0 < N_NODES; nb0 += gridDim.x * 32) {
        int nb = nb0 + warp * 8;

#pragma unroll
        for (int q = 0; q < 8; q++) {
            int node = nb + q;
            if (node < N_NODES) {
                size_t r = (size_t)node * 64;
                sMX[warp][q][lane]      = make_float2(g_mean[r + lane],      x[r + lane]);
                sMX[warp][q][lane + 32] = make_float2(g_mean[r + lane + 32], x[r + lane + 32]);
            } else {
                sMX[warp][q][lane]      = make_float2(0.f, 0.f);
                sMX[warp][q][lane + 32] = make_float2(0.f, 0.f);
            }
        }
        __syncwarp();

        unsigned long long accA[8], accB[8];
#pragma unroll
        for (int q = 0; q < 8; q++) { accA[q] = pk(0.f, 0.f); accB[q] = pk(0.f, 0.f); }

#pragma unroll 4
        for (int k2 = 0; k2 < 32; k2++) {
            int k = k2 * 2;
            float2 wa0 = sWA[k][lane];
            float2 wb0 = sWA[k][lane + 32];
            float2 wa1 = sWA[k + 1][lane];
            float2 wb1 = sWA[k + 1][lane + 32];
            unsigned long long WA0 = pk(wa0.x, wa0.y), WB0 = pk(wb0.x, wb0.y);
            unsigned long long WA1 = pk(wa1.x, wa1.y), WB1 = pk(wb1.x, wb1.y);
#pragma unroll
            for (int q = 0; q < 8; q++) {
                float4 mx = *reinterpret_cast<const float4*>(&sMX[warp][q][k]);
                unsigned long long m0 = pk(mx.x, mx.y);
                unsigned long long m1 = pk(mx.z, mx.w);
                fma2(accA[q], m0, WA0);
                fma2(accB[q], m0, WB0);
                fma2(accA[q], m1, WA1);
                fma2(accB[q], m1, WB1);
            }
        }
        __syncwarp();

#pragma unroll
        for (int q = 0; q < 8; q++) {
            int node = nb + q;
            if (node < N_NODES) {
                float2 A = upk(accA[q]);
                float2 B = upk(accB[q]);
                float h0 = fmaxf(A.x + A.y + sb1[lane], 0.f);
                float h1 = fmaxf(B.x + B.y + sb1[lane + 32], 0.f);
                size_t r = (size_t)node * 64;
                g_h[r + lane]      = h0;
                g_h[r + lane + 32] = h1;
                float* sH = reinterpret_cast<float*>(&sMX[warp][q][0]);
                sH[lane]      = h0;
                sH[lane + 32] = h1;
            }
        }
        __syncwarp();

        {
            int n = lane >> 2, c0 = (lane & 3) * 4;
            int node = nb + n;
            if (node < N_NODES) {
                const float* hrow = reinterpret_cast<const float*>(&sMX[warp][n][0]);
                unsigned long long P01 = pk(0.f, 0.f), P23 = pk(0.f, 0.f);
#pragma unroll
                for (int k = 0; k < 64; k++) {
                    float hv = hrow[k];
                    unsigned long long hd = pk(hv, hv);
                    unsigned long long w01 =
                        *reinterpret_cast<const unsigned long long*>(&sW2[k * 16 + c0]);
                    unsigned long long w23 =
                        *reinterpret_cast<const unsigned long long*>(&sW2[k * 16 + c0 + 2]);
                    fma2(P01, hd, w01);
                    fma2(P23, hd, w23);
                }
                float2 p01 = upk(P01), p23 = upk(P23);
                *reinterpret_cast<float4*>(g_p + (size_t)node * 16 + c0) =
                    make_float4(p01.x, p01.y, p23.x, p23.y);
            }
        }
        __syncwarp();
    }
}

// ---------------------------------------------------------------------------
// Final: out = g_pm + h @ W2_r + b2
// ---------------------------------------------------------------------------
__global__ void final_k(const float* __restrict__ W2r,
                        const float* __restrict__ b2,
                        float* __restrict__ out) {
    __shared__ float sW[64 * 16];
    __shared__ float sb[16];
    __shared__ float sh[4][4][64];
    int tid = threadIdx.x, warp = tid >> 5, lane = tid & 31;
    for (int i = tid; i < 1024; i += 128) sW[i] = W2r[i];
    if (tid < 16) sb[tid] = b2[tid];
    __syncthreads();

    int n = lane >> 3, c0 = (lane & 7) * 2;
    for (int nb = (blockIdx.x * 4 + warp) * 4; nb < N_NODES; nb += gridDim.x * 16) {
        int nvalid = min(4, N_NODES - nb);
        for (int q = 0; q < nvalid; q++) {
            size_t r = (size_t)(nb + q) * 64;
            sh[warp][q][lane]      = g_h[r + lane];
            sh[warp][q][lane + 32] = g_h[r + lane + 32];
        }
        __syncwarp();
        if (n < nvalid) {
            int node = nb + n;
            float2 pm = *reinterpret_cast<const float2*>(g_pm + (size_t)node * 16 + c0);
            float p0 = sb[c0]     + pm.x;
            float p1 = sb[c0 + 1] + pm.y;
#pragma unroll
            for (int k = 0; k < 64; k++) {
                float hv = sh[warp][n][k];
                p0 = fmaf(hv, sW[k * 16 + c0], p0);
                p1 = fmaf(hv, sW[k * 16 + c0 + 1], p1);
            }
            out[(size_t)node * 16 + c0]     = p0;
            out[(size_t)node * 16 + c0 + 1] = p1;
        }
        __syncwarp();
    }
}

// ---------------------------------------------------------------------------
extern "C" void kernel_launch(void* const* d_in, const int* in_sizes, int n_in,
                              void* d_out, int out_size) {
    const float* x   = (const float*)d_in[0];
    const int*   ei  = (const int*)d_in[1];     // int32 (JAX x64 disabled)
    const float* W1l = (const float*)d_in[2];
    const float* b1  = (const float*)d_in[3];
    const float* W1r = (const float*)d_in[4];
    const float* W2l = (const float*)d_in[5];
    const float* b2  = (const float*)d_in[6];
    const float* W2r = (const float*)d_in[7];
    float* out = (float*)d_out;

    zero_cnt_k<<<(N_NODES + 255) / 256, 256>>>();
    fill_k<<<(N_EDGES + 255) / 256, 256>>>(ei);
    gather_mean_k<0, 4><<<(N_NODES * 16 + 255) / 256, 256>>>((const float4*)x);
    layer1_k<<<592, 128>>>(x, W1l, b1, W1r, W2l);
    gather_mean_k<1, 2><<<(N_NODES * 4 + 255) / 256, 256>>>(nullptr);
    final_k<<<592, 128>>>(W2r, b2, out);
}